// round 1
// baseline (speedup 1.0000x reference)
#include <cuda_runtime.h>
#include <cuda_bf16.h>
#include <math.h>

// Problem constants (match reference)
#define NN   50000
#define EE   1600000
#define ETOT (EE + NN)      // with self-loops
#define INC  64
#define HID  16
#define HEADS 8
#define C1   (HEADS * HID)  // 128
#define OUTC 32
#define BG   256
#define SLOPE 0.2f

// ---------------- scratch (device globals; no allocation allowed) ------------
__device__ float g_xl1[NN * C1];
__device__ float g_xr1[NN * C1];
__device__ float g_out1[NN * C1];     // aggregated layer1 output, then h1 in place
__device__ float g_aexp1[(size_t)ETOT * HEADS];
__device__ float g_dn1[NN * HEADS];
__device__ float g_xl2[NN * HID];
__device__ float g_xr2[NN * HID];
__device__ float g_out2[NN * HID];
__device__ float g_aexp2[ETOT];
__device__ float g_dn2[NN];
__device__ float g_pool[BG * HID];
__device__ float g_cnt[BG];

__device__ __forceinline__ float elu1(float v) { return v > 0.f ? v : (expf(v) - 1.f); }
__device__ __forceinline__ float lrelu(float v) { return v > 0.f ? v : SLOPE * v; }

// ---------------- zero scratch ----------------------------------------------
__global__ void zero_scratch() {
    int i = blockIdx.x * blockDim.x + threadIdx.x;
    int stride = gridDim.x * blockDim.x;
    for (int j = i; j < NN * C1; j += stride) g_out1[j] = 0.f;
    for (int j = i; j < NN * HID; j += stride) g_out2[j] = 0.f;
    for (int j = i; j < NN * HEADS; j += stride) g_dn1[j] = 0.f;
    for (int j = i; j < NN; j += stride) g_dn2[j] = 0.f;
    if (i < BG * HID) g_pool[i] = 0.f;
    if (i < BG) g_cnt[i] = 0.f;
}

// ---------------- layer 1: node transforms xl1 = x@wl1+bl1, xr1 = x@wr1+br1 --
__global__ void transform1(const float* __restrict__ x,
                           const float* __restrict__ wl, const float* __restrict__ bl,
                           const float* __restrict__ wr, const float* __restrict__ br) {
    int n = blockIdx.x;           // one node per block
    int j = threadIdx.x;          // 128 output channels
    __shared__ float sx[INC];
    if (j < INC) sx[j] = x[n * INC + j];
    __syncthreads();
    float sl = bl[j], sr = br[j];
#pragma unroll 8
    for (int k = 0; k < INC; k++) {
        float xv = sx[k];
        sl = fmaf(xv, wl[k * C1 + j], sl);
        sr = fmaf(xv, wr[k * C1 + j], sr);
    }
    g_xl1[n * C1 + j] = sl;
    g_xr1[n * C1 + j] = sr;
}

// ---------------- layer 1: edge logits + exp + denom -------------------------
__global__ void edge1_logits(const int* __restrict__ ei, const float* __restrict__ att) {
    int tid = blockIdx.x * blockDim.x + threadIdx.x;
    if (tid >= ETOT * HEADS) return;
    int e = tid >> 3, h = tid & 7;
    int src, dst;
    if (e < EE) { src = ei[e]; dst = ei[EE + e]; }
    else        { src = dst = e - EE; }
    const float4* xl = (const float4*)(g_xl1 + src * C1 + h * HID);
    const float4* xr = (const float4*)(g_xr1 + dst * C1 + h * HID);
    const float4* at = (const float4*)(att + h * HID);
    float s = 0.f;
#pragma unroll
    for (int i = 0; i < 4; i++) {
        float4 a = xl[i], b = xr[i], w = at[i];
        s = fmaf(w.x, lrelu(a.x + b.x), s);
        s = fmaf(w.y, lrelu(a.y + b.y), s);
        s = fmaf(w.z, lrelu(a.z + b.z), s);
        s = fmaf(w.w, lrelu(a.w + b.w), s);
    }
    // logits are O(1); softmax is shift-invariant so no max pass needed
    float a = expf(s);
    g_aexp1[tid] = a;
    atomicAdd(&g_dn1[dst * HEADS + h], a);
}

// ---------------- layer 1: weighted scatter-add ------------------------------
__global__ void edge1_agg(const int* __restrict__ ei) {
    int tid = blockIdx.x * blockDim.x + threadIdx.x;
    if (tid >= ETOT * HEADS) return;
    int e = tid >> 3, h = tid & 7;
    int src, dst;
    if (e < EE) { src = ei[e]; dst = ei[EE + e]; }
    else        { src = dst = e - EE; }
    float alpha = g_aexp1[tid] / (g_dn1[dst * HEADS + h] + 1e-16f);
    const float4* xl = (const float4*)(g_xl1 + src * C1 + h * HID);
    float4* out = (float4*)(g_out1 + dst * C1 + h * HID);
#pragma unroll
    for (int i = 0; i < 4; i++) {
        float4 v = xl[i];
        v.x *= alpha; v.y *= alpha; v.z *= alpha; v.w *= alpha;
        atomicAdd(out + i, v);
    }
}

// ---------------- layer 1: bias + ELU (in place) -----------------------------
__global__ void bias_elu1(const float* __restrict__ bias) {
    int i = blockIdx.x * blockDim.x + threadIdx.x;
    if (i >= NN * C1) return;
    g_out1[i] = elu1(g_out1[i] + bias[i & (C1 - 1)]);
}

// ---------------- layer 2: node transforms (128 -> 16, two mats) -------------
__global__ void transform2(const float* __restrict__ wl, const float* __restrict__ bl,
                           const float* __restrict__ wr, const float* __restrict__ br) {
    int t = blockIdx.x * blockDim.x + threadIdx.x;
    if (t >= NN * HID) return;
    int n = t >> 4, k = t & 15;
    const float* hr = g_out1 + n * C1;
    float sl = bl[k], sr = br[k];
#pragma unroll 8
    for (int j = 0; j < C1; j++) {
        float hv = hr[j];
        sl = fmaf(hv, wl[j * HID + k], sl);
        sr = fmaf(hv, wr[j * HID + k], sr);
    }
    g_xl2[t] = sl;
    g_xr2[t] = sr;
}

// ---------------- layer 2: edge logits + exp + denom (1 head) ----------------
__global__ void edge2_logits(const int* __restrict__ ei, const float* __restrict__ att) {
    int e = blockIdx.x * blockDim.x + threadIdx.x;
    if (e >= ETOT) return;
    int src, dst;
    if (e < EE) { src = ei[e]; dst = ei[EE + e]; }
    else        { src = dst = e - EE; }
    const float4* xl = (const float4*)(g_xl2 + src * HID);
    const float4* xr = (const float4*)(g_xr2 + dst * HID);
    const float4* at = (const float4*)att;
    float s = 0.f;
#pragma unroll
    for (int i = 0; i < 4; i++) {
        float4 a = xl[i], b = xr[i], w = at[i];
        s = fmaf(w.x, lrelu(a.x + b.x), s);
        s = fmaf(w.y, lrelu(a.y + b.y), s);
        s = fmaf(w.z, lrelu(a.z + b.z), s);
        s = fmaf(w.w, lrelu(a.w + b.w), s);
    }
    float a = expf(s);
    g_aexp2[e] = a;
    atomicAdd(&g_dn2[dst], a);
}

// ---------------- layer 2: weighted scatter-add ------------------------------
__global__ void edge2_agg(const int* __restrict__ ei) {
    int e = blockIdx.x * blockDim.x + threadIdx.x;
    if (e >= ETOT) return;
    int src, dst;
    if (e < EE) { src = ei[e]; dst = ei[EE + e]; }
    else        { src = dst = e - EE; }
    float alpha = g_aexp2[e] / (g_dn2[dst] + 1e-16f);
    const float4* xl = (const float4*)(g_xl2 + src * HID);
    float4* out = (float4*)(g_out2 + dst * HID);
#pragma unroll
    for (int i = 0; i < 4; i++) {
        float4 v = xl[i];
        v.x *= alpha; v.y *= alpha; v.z *= alpha; v.w *= alpha;
        atomicAdd(out + i, v);
    }
}

// ---------------- layer 2 epilogue + mean-pool accumulation ------------------
__global__ void post2_pool(const float* __restrict__ bias, const int* __restrict__ batch) {
    int t = blockIdx.x * blockDim.x + threadIdx.x;
    if (t >= NN * HID) return;
    int n = t >> 4, k = t & 15;
    float v = elu1(g_out2[t] + bias[k]);
    int g = batch[n];
    atomicAdd(&g_pool[g * HID + k], v);
    if (k == 0) atomicAdd(&g_cnt[g], 1.f);
}

// ---------------- mean + MLP -------------------------------------------------
__global__ void mlp_kernel(const float* __restrict__ w1, const float* __restrict__ b1,
                           const float* __restrict__ w2, const float* __restrict__ b2,
                           const float* __restrict__ w3, const float* __restrict__ b3,
                           float* __restrict__ out) {
    int g = blockIdx.x * blockDim.x + threadIdx.x;
    if (g >= BG) return;
    float cnt = fmaxf(g_cnt[g], 1.f);
    float h[HID];
#pragma unroll
    for (int k = 0; k < HID; k++) h[k] = g_pool[g * HID + k] / cnt;
    float t1[2 * HID];
#pragma unroll
    for (int j = 0; j < 2 * HID; j++) {
        float s = b1[j];
#pragma unroll
        for (int k = 0; k < HID; k++) s = fmaf(h[k], w1[k * 2 * HID + j], s);
        t1[j] = elu1(s);
    }
    float t2[HID];
#pragma unroll
    for (int k = 0; k < HID; k++) {
        float s = b2[k];
#pragma unroll
        for (int j = 0; j < 2 * HID; j++) s = fmaf(t1[j], w2[j * HID + k], s);
        t2[k] = elu1(s);
    }
#pragma unroll
    for (int o = 0; o < OUTC; o++) {
        float s = b3[o];
#pragma unroll
        for (int k = 0; k < HID; k++) s = fmaf(t2[k], w3[k * OUTC + o], s);
        out[g * OUTC + o] = s;
    }
}

// ---------------- launch -----------------------------------------------------
extern "C" void kernel_launch(void* const* d_in, const int* in_sizes, int n_in,
                              void* d_out, int out_size) {
    const float* x    = (const float*)d_in[0];
    const int*   ei   = (const int*)  d_in[1];
    const int*   batch= (const int*)  d_in[2];
    const float* wl1  = (const float*)d_in[3];
    const float* bl1  = (const float*)d_in[4];
    const float* wr1  = (const float*)d_in[5];
    const float* br1  = (const float*)d_in[6];
    const float* att1 = (const float*)d_in[7];
    const float* bias1= (const float*)d_in[8];
    const float* wl2  = (const float*)d_in[9];
    const float* bl2  = (const float*)d_in[10];
    const float* wr2  = (const float*)d_in[11];
    const float* br2  = (const float*)d_in[12];
    const float* att2 = (const float*)d_in[13];
    const float* bias2= (const float*)d_in[14];
    const float* w_m1 = (const float*)d_in[15];
    const float* b_m1 = (const float*)d_in[16];
    const float* w_m2 = (const float*)d_in[17];
    const float* b_m2 = (const float*)d_in[18];
    const float* w_m3 = (const float*)d_in[19];
    const float* b_m3 = (const float*)d_in[20];
    float* out = (float*)d_out;

    const int TB = 256;

    zero_scratch<<<592, TB>>>();                       // ~148 SMs * 4 blocks
    transform1<<<NN, C1>>>(x, wl1, bl1, wr1, br1);
    edge1_logits<<<(ETOT * HEADS + TB - 1) / TB, TB>>>(ei, att1);
    edge1_agg<<<(ETOT * HEADS + TB - 1) / TB, TB>>>(ei);
    bias_elu1<<<(NN * C1 + TB - 1) / TB, TB>>>(bias1);
    transform2<<<(NN * HID + TB - 1) / TB, TB>>>(wl2, bl2, wr2, br2);
    edge2_logits<<<(ETOT + TB - 1) / TB, TB>>>(ei, att2);
    edge2_agg<<<(ETOT + TB - 1) / TB, TB>>>(ei);
    post2_pool<<<(NN * HID + TB - 1) / TB, TB>>>(bias2, batch);
    mlp_kernel<<<1, BG>>>(w_m1, b_m1, w_m2, b_m2, w_m3, b_m3, out);
}

// round 3
// speedup vs baseline: 1.2377x; 1.2377x over previous
#include <cuda_runtime.h>
#include <cuda_bf16.h>
#include <math.h>

// Problem constants (match reference)
#define NN   50000
#define EE   1600000
#define ETOT (EE + NN)      // with self-loops
#define INC  64
#define HID  16
#define HEADS 8
#define C1   (HEADS * HID)  // 128
#define OUTC 32
#define BG   256
#define SLOPE 0.2f

// ---------------- scratch (device globals; no allocation allowed) ------------
__device__ float g_xl1[NN * C1];
__device__ float g_xr1[NN * C1];
__device__ float g_out1[NN * C1];     // Σ a*xl accum, then h1 in place
__device__ float g_dn1[NN * HEADS];
__device__ float g_xl2[NN * HID];
__device__ float g_xr2[NN * HID];
__device__ float g_out2[NN * HID];
__device__ float g_dn2[NN];
__device__ float g_pool[BG * HID];
__device__ float g_cnt[BG];

__device__ __forceinline__ float elu1(float v) { return v > 0.f ? v : (expf(v) - 1.f); }
__device__ __forceinline__ float lrelu(float v) { return v > 0.f ? v : SLOPE * v; }

// ---------------- zero scratch ----------------------------------------------
__global__ void zero_scratch() {
    int i = blockIdx.x * blockDim.x + threadIdx.x;
    int stride = gridDim.x * blockDim.x;
    for (int j = i; j < NN * C1; j += stride) g_out1[j] = 0.f;
    for (int j = i; j < NN * HID; j += stride) g_out2[j] = 0.f;
    for (int j = i; j < NN * HEADS; j += stride) g_dn1[j] = 0.f;
    for (int j = i; j < NN; j += stride) g_dn2[j] = 0.f;
    if (i < BG * HID) g_pool[i] = 0.f;
    if (i < BG) g_cnt[i] = 0.f;
}

// ---------------- layer 1: node transforms xl1 = x@wl1+bl1, xr1 = x@wr1+br1 --
__global__ void transform1(const float* __restrict__ x,
                           const float* __restrict__ wl, const float* __restrict__ bl,
                           const float* __restrict__ wr, const float* __restrict__ br) {
    int n = blockIdx.x;           // one node per block
    int j = threadIdx.x;          // 128 output channels
    __shared__ float sx[INC];
    if (j < INC) sx[j] = x[n * INC + j];
    __syncthreads();
    float sl = bl[j], sr = br[j];
#pragma unroll 8
    for (int k = 0; k < INC; k++) {
        float xv = sx[k];
        sl = fmaf(xv, wl[k * C1 + j], sl);
        sr = fmaf(xv, wr[k * C1 + j], sr);
    }
    g_xl1[n * C1 + j] = sl;
    g_xr1[n * C1 + j] = sr;
}

// ---------------- layer 1: fused edge pass -----------------------------------
// alpha normalization is linear per dst: out = (Σ a*xl_src)/denom, so one pass:
// accumulate a into denom and a*xl into out simultaneously.
__global__ void edge1_fused(const int* __restrict__ ei, const float* __restrict__ att) {
    int tid = blockIdx.x * blockDim.x + threadIdx.x;
    if (tid >= ETOT * HEADS) return;
    int e = tid >> 3, h = tid & 7;
    int src, dst;
    if (e < EE) { src = ei[e]; dst = ei[EE + e]; }
    else        { src = dst = e - EE; }
    const float4* xl = (const float4*)(g_xl1 + src * C1 + h * HID);
    const float4* xr = (const float4*)(g_xr1 + dst * C1 + h * HID);
    const float4* at = (const float4*)(att + h * HID);
    float4 l[4];
    float s = 0.f;
#pragma unroll
    for (int i = 0; i < 4; i++) {
        float4 a = xl[i]; l[i] = a;
        float4 b = xr[i], w = at[i];
        s = fmaf(w.x, lrelu(a.x + b.x), s);
        s = fmaf(w.y, lrelu(a.y + b.y), s);
        s = fmaf(w.z, lrelu(a.z + b.z), s);
        s = fmaf(w.w, lrelu(a.w + b.w), s);
    }
    // logits are O(1); softmax is shift-invariant so no max pass needed
    float a = expf(s);
    atomicAdd(&g_dn1[dst * HEADS + h], a);
    float4* out = (float4*)(g_out1 + dst * C1 + h * HID);
#pragma unroll
    for (int i = 0; i < 4; i++) {
        float4 v = l[i];
        v.x *= a; v.y *= a; v.z *= a; v.w *= a;
        atomicAdd(out + i, v);
    }
}

// ---------------- layer 1: normalize + bias + ELU (in place) -----------------
__global__ void bias_elu1(const float* __restrict__ bias) {
    int i = blockIdx.x * blockDim.x + threadIdx.x;
    if (i >= NN * C1) return;
    int c = i & (C1 - 1);
    int nh = (i >> 7) * HEADS + (c >> 4);   // node*HEADS + head
    float dn = g_dn1[nh] + 1e-16f;
    g_out1[i] = elu1(g_out1[i] / dn + bias[c]);
}

// ---------------- layer 2: node transforms (128 -> 16, two mats) -------------
__global__ void transform2(const float* __restrict__ wl, const float* __restrict__ bl,
                           const float* __restrict__ wr, const float* __restrict__ br) {
    int t = blockIdx.x * blockDim.x + threadIdx.x;
    if (t >= NN * HID) return;
    int n = t >> 4, k = t & 15;
    const float* hr = g_out1 + n * C1;
    float sl = bl[k], sr = br[k];
#pragma unroll 8
    for (int j = 0; j < C1; j++) {
        float hv = hr[j];
        sl = fmaf(hv, wl[j * HID + k], sl);
        sr = fmaf(hv, wr[j * HID + k], sr);
    }
    g_xl2[t] = sl;
    g_xr2[t] = sr;
}

// ---------------- layer 2: fused edge pass (1 head) --------------------------
__global__ void edge2_fused(const int* __restrict__ ei, const float* __restrict__ att) {
    int e = blockIdx.x * blockDim.x + threadIdx.x;
    if (e >= ETOT) return;
    int src, dst;
    if (e < EE) { src = ei[e]; dst = ei[EE + e]; }
    else        { src = dst = e - EE; }
    const float4* xl = (const float4*)(g_xl2 + src * HID);
    const float4* xr = (const float4*)(g_xr2 + dst * HID);
    const float4* at = (const float4*)att;
    float4 l[4];
    float s = 0.f;
#pragma unroll
    for (int i = 0; i < 4; i++) {
        float4 a = xl[i]; l[i] = a;
        float4 b = xr[i], w = at[i];
        s = fmaf(w.x, lrelu(a.x + b.x), s);
        s = fmaf(w.y, lrelu(a.y + b.y), s);
        s = fmaf(w.z, lrelu(a.z + b.z), s);
        s = fmaf(w.w, lrelu(a.w + b.w), s);
    }
    float a = expf(s);
    atomicAdd(&g_dn2[dst], a);
    float4* out = (float4*)(g_out2 + dst * HID);
#pragma unroll
    for (int i = 0; i < 4; i++) {
        float4 v = l[i];
        v.x *= a; v.y *= a; v.z *= a; v.w *= a;
        atomicAdd(out + i, v);
    }
}

// ---------------- layer 2 epilogue (normalize) + mean-pool accumulation ------
__global__ void post2_pool(const float* __restrict__ bias, const int* __restrict__ batch) {
    int t = blockIdx.x * blockDim.x + threadIdx.x;
    if (t >= NN * HID) return;
    int n = t >> 4, k = t & 15;
    float dn = g_dn2[n] + 1e-16f;
    float v = elu1(g_out2[t] / dn + bias[k]);
    int g = batch[n];
    atomicAdd(&g_pool[g * HID + k], v);
    if (k == 0) atomicAdd(&g_cnt[g], 1.f);
}

// ---------------- mean + MLP -------------------------------------------------
__global__ void mlp_kernel(const float* __restrict__ w1, const float* __restrict__ b1,
                           const float* __restrict__ w2, const float* __restrict__ b2,
                           const float* __restrict__ w3, const float* __restrict__ b3,
                           float* __restrict__ out) {
    int g = blockIdx.x * blockDim.x + threadIdx.x;
    if (g >= BG) return;
    float cnt = fmaxf(g_cnt[g], 1.f);
    float h[HID];
#pragma unroll
    for (int k = 0; k < HID; k++) h[k] = g_pool[g * HID + k] / cnt;
    float t1[2 * HID];
#pragma unroll
    for (int j = 0; j < 2 * HID; j++) {
        float s = b1[j];
#pragma unroll
        for (int k = 0; k < HID; k++) s = fmaf(h[k], w1[k * 2 * HID + j], s);
        t1[j] = elu1(s);
    }
    float t2[HID];
#pragma unroll
    for (int k = 0; k < HID; k++) {
        float s = b2[k];
#pragma unroll
        for (int j = 0; j < 2 * HID; j++) s = fmaf(t1[j], w2[j * HID + k], s);
        t2[k] = elu1(s);
    }
#pragma unroll
    for (int o = 0; o < OUTC; o++) {
        float s = b3[o];
#pragma unroll
        for (int k = 0; k < HID; k++) s = fmaf(t2[k], w3[k * OUTC + o], s);
        out[g * OUTC + o] = s;
    }
}

// ---------------- launch -----------------------------------------------------
extern "C" void kernel_launch(void* const* d_in, const int* in_sizes, int n_in,
                              void* d_out, int out_size) {
    const float* x    = (const float*)d_in[0];
    const int*   ei   = (const int*)  d_in[1];
    const int*   batch= (const int*)  d_in[2];
    const float* wl1  = (const float*)d_in[3];
    const float* bl1  = (const float*)d_in[4];
    const float* wr1  = (const float*)d_in[5];
    const float* br1  = (const float*)d_in[6];
    const float* att1 = (const float*)d_in[7];
    const float* bias1= (const float*)d_in[8];
    const float* wl2  = (const float*)d_in[9];
    const float* bl2  = (const float*)d_in[10];
    const float* wr2  = (const float*)d_in[11];
    const float* br2  = (const float*)d_in[12];
    const float* att2 = (const float*)d_in[13];
    const float* bias2= (const float*)d_in[14];
    const float* w_m1 = (const float*)d_in[15];
    const float* b_m1 = (const float*)d_in[16];
    const float* w_m2 = (const float*)d_in[17];
    const float* b_m2 = (const float*)d_in[18];
    const float* w_m3 = (const float*)d_in[19];
    const float* b_m3 = (const float*)d_in[20];
    float* out = (float*)d_out;

    const int TB = 256;

    zero_scratch<<<592, TB>>>();
    transform1<<<NN, C1>>>(x, wl1, bl1, wr1, br1);
    edge1_fused<<<(ETOT * HEADS + TB - 1) / TB, TB>>>(ei, att1);
    bias_elu1<<<(NN * C1 + TB - 1) / TB, TB>>>(bias1);
    transform2<<<(NN * HID + TB - 1) / TB, TB>>>(wl2, bl2, wr2, br2);
    edge2_fused<<<(ETOT + TB - 1) / TB, TB>>>(ei, att2);
    post2_pool<<<(NN * HID + TB - 1) / TB, TB>>>(bias2, batch);
    mlp_kernel<<<1, BG>>>(w_m1, b_m1, w_m2, b_m2, w_m3, b_m3, out);
}

// round 4
// speedup vs baseline: 2.2464x; 1.8150x over previous
#include <cuda_runtime.h>
#include <cuda_bf16.h>
#include <math.h>

// Problem constants (match reference)
#define NN   50000
#define EE   1600000
#define INC  64
#define HID  16
#define HEADS 8
#define C1   (HEADS * HID)  // 128
#define OUTC 32
#define BG   256
#define SLOPE 0.2f

// ---------------- scratch (device globals; no allocation allowed) ------------
__device__ __align__(16) float g_xl1[NN * C1];
__device__ __align__(16) float g_xr1[NN * C1];
__device__ __align__(16) float g_out1[NN * C1];   // final h1 after gat1_gather
__device__ __align__(16) float g_xl2[NN * HID];
__device__ __align__(16) float g_xr2[NN * HID];
__device__ __align__(16) float g_pool[BG * HID];
__device__ float g_cnt[BG];
// CSR scratch
__device__ int g_count[NN];
__device__ int g_cursor[NN];
__device__ int g_rowstart[NN + 1];
__device__ int g_srcs[EE];

__device__ __forceinline__ float elu1(float v) { return v > 0.f ? v : (__expf(v) - 1.f); }
__device__ __forceinline__ float lrelu(float v) { return v > 0.f ? v : SLOPE * v; }

// ---------------- zero small scratch -----------------------------------------
__global__ void zero_small() {
    int i = blockIdx.x * blockDim.x + threadIdx.x;
    int stride = gridDim.x * blockDim.x;
    for (int j = i; j < NN; j += stride) g_count[j] = 0;
    if (i < BG * HID) g_pool[i] = 0.f;
    if (i < BG) g_cnt[i] = 0.f;
}

// ---------------- CSR build: histogram / scan / fill -------------------------
__global__ void csr_hist(const int* __restrict__ ei) {
    int e = blockIdx.x * blockDim.x + threadIdx.x;
    if (e >= EE) return;
    atomicAdd(&g_count[ei[EE + e]], 1);
}

__global__ void csr_scan() {
    __shared__ int partial[1024];
    const int CH = (NN + 1023) / 1024;   // 49
    int t = threadIdx.x;
    int lo = t * CH, hi = min(lo + CH, NN);
    int s = 0;
    for (int i = lo; i < hi; i++) s += g_count[i];
    partial[t] = s;
    __syncthreads();
    // Hillis-Steele inclusive scan
    for (int off = 1; off < 1024; off <<= 1) {
        int v = (t >= off) ? partial[t - off] : 0;
        __syncthreads();
        partial[t] += v;
        __syncthreads();
    }
    int run = (t == 0) ? 0 : partial[t - 1];
    for (int i = lo; i < hi; i++) {
        g_rowstart[i] = run;
        g_cursor[i] = run;
        run += g_count[i];
    }
    if (t == 0) g_rowstart[NN] = partial[1023];
}

__global__ void csr_fill(const int* __restrict__ ei) {
    int e = blockIdx.x * blockDim.x + threadIdx.x;
    if (e >= EE) return;
    int src = ei[e], dst = ei[EE + e];
    int pos = atomicAdd(&g_cursor[dst], 1);
    g_srcs[pos] = src;
}

// ---------------- layer 1: node transforms, 16 nodes per block ---------------
__global__ void transform1_tiled(const float* __restrict__ x,
                                 const float* __restrict__ wl, const float* __restrict__ bl,
                                 const float* __restrict__ wr, const float* __restrict__ br) {
    __shared__ float sx[16 * INC];
    int j = threadIdx.x;            // output channel 0..127
    int n0 = blockIdx.x * 16;
    const float* xb = x + n0 * INC;
#pragma unroll
    for (int i = 0; i < 8; i++) sx[j + i * 128] = xb[j + i * 128];
    __syncthreads();
    float blv = bl[j], brv = br[j];
    float sl[16], sr[16];
#pragma unroll
    for (int t = 0; t < 16; t++) { sl[t] = blv; sr[t] = brv; }
#pragma unroll 4
    for (int k = 0; k < INC; k++) {
        float wlv = wl[k * C1 + j];
        float wrv = wr[k * C1 + j];
#pragma unroll
        for (int t = 0; t < 16; t++) {
            float xv = sx[t * INC + k];
            sl[t] = fmaf(xv, wlv, sl[t]);
            sr[t] = fmaf(xv, wrv, sr[t]);
        }
    }
#pragma unroll
    for (int t = 0; t < 16; t++) {
        g_xl1[(n0 + t) * C1 + j] = sl[t];
        g_xr1[(n0 + t) * C1 + j] = sr[t];
    }
}

// ---------------- layer 1: warp-per-node gather (no atomics) -----------------
// lane l owns channels 4l..4l+3; lanes 4h..4h+3 cover head h (16 channels).
// Softmax normalization is linear per dst, so: out = (sum a*xl_src)/(sum a).
__global__ void gat1_gather(const float* __restrict__ att, const float* __restrict__ bias) {
    int warp = (blockIdx.x * blockDim.x + threadIdx.x) >> 5;
    if (warp >= NN) return;
    int lane = threadIdx.x & 31;
    int n = warp;
    int c = lane * 4;
    float4 at = *(const float4*)(att + c);
    float4 xr = *(const float4*)(g_xr1 + n * C1 + c);
    float4 acc = make_float4(0.f, 0.f, 0.f, 0.f);
    float dn = 0.f;
    int start = g_rowstart[n], end = g_rowstart[n + 1];
    // virtual edge list: [self] + CSR edges
    for (int idx = start - 1; idx < end; idx++) {
        int src = (idx < start) ? n : g_srcs[idx];
        float4 xl = *(const float4*)(g_xl1 + src * C1 + c);
        float p;
        p = at.x * lrelu(xl.x + xr.x);
        p = fmaf(at.y, lrelu(xl.y + xr.y), p);
        p = fmaf(at.z, lrelu(xl.z + xr.z), p);
        p = fmaf(at.w, lrelu(xl.w + xr.w), p);
        p += __shfl_xor_sync(0xffffffffu, p, 1);
        p += __shfl_xor_sync(0xffffffffu, p, 2);   // head logit, same on 4-lane group
        float a = __expf(p);                       // shift-invariant softmax, logits O(1)
        dn += a;
        acc.x = fmaf(a, xl.x, acc.x);
        acc.y = fmaf(a, xl.y, acc.y);
        acc.z = fmaf(a, xl.z, acc.z);
        acc.w = fmaf(a, xl.w, acc.w);
    }
    float inv = 1.f / (dn + 1e-16f);
    float4 b = *(const float4*)(bias + c);
    float4 o;
    o.x = elu1(fmaf(acc.x, inv, b.x));
    o.y = elu1(fmaf(acc.y, inv, b.y));
    o.z = elu1(fmaf(acc.z, inv, b.z));
    o.w = elu1(fmaf(acc.w, inv, b.w));
    *(float4*)(g_out1 + n * C1 + c) = o;
}

// ---------------- layer 2: node transforms (128 -> 16, two mats) -------------
__global__ void transform2(const float* __restrict__ wl, const float* __restrict__ bl,
                           const float* __restrict__ wr, const float* __restrict__ br) {
    int t = blockIdx.x * blockDim.x + threadIdx.x;
    if (t >= NN * HID) return;
    int n = t >> 4, k = t & 15;
    const float* hr = g_out1 + n * C1;
    float sl = bl[k], sr = br[k];
#pragma unroll 8
    for (int j = 0; j < C1; j++) {
        float hv = hr[j];
        sl = fmaf(hv, wl[j * HID + k], sl);
        sr = fmaf(hv, wr[j * HID + k], sr);
    }
    g_xl2[t] = sl;
    g_xr2[t] = sr;
}

// ---------------- layer 2: warp-per-node gather + fused mean-pool ------------
// lane layout: slot = lane>>2 (8 parallel edges), cg = (lane&3)*4 (channel base).
__global__ void gat2_gather(const float* __restrict__ att2, const float* __restrict__ bias2,
                            const int* __restrict__ batch) {
    int warp = (blockIdx.x * blockDim.x + threadIdx.x) >> 5;
    if (warp >= NN) return;
    int lane = threadIdx.x & 31;
    int n = warp;
    int slot = lane >> 2;
    int cg = (lane & 3) * 4;
    float4 at = *(const float4*)(att2 + cg);
    float4 xr = *(const float4*)(g_xr2 + n * HID + cg);
    float4 acc = make_float4(0.f, 0.f, 0.f, 0.f);
    float dn = 0.f;
    int start = g_rowstart[n], end = g_rowstart[n + 1];
    // virtual list: [self] + edges, 8 per iteration
    for (int base = start - 1 + slot; base - slot < end; base += 8) {
        int idx = base;
        bool valid = idx < end;
        int src = (!valid || idx < start) ? n : g_srcs[idx];
        float4 xl = *(const float4*)(g_xl2 + src * HID + cg);
        float p;
        p = at.x * lrelu(xl.x + xr.x);
        p = fmaf(at.y, lrelu(xl.y + xr.y), p);
        p = fmaf(at.z, lrelu(xl.z + xr.z), p);
        p = fmaf(at.w, lrelu(xl.w + xr.w), p);
        p += __shfl_xor_sync(0xffffffffu, p, 1);
        p += __shfl_xor_sync(0xffffffffu, p, 2);   // full 16-ch logit for this edge
        float a = valid ? __expf(p) : 0.f;
        dn += a;
        acc.x = fmaf(a, xl.x, acc.x);
        acc.y = fmaf(a, xl.y, acc.y);
        acc.z = fmaf(a, xl.z, acc.z);
        acc.w = fmaf(a, xl.w, acc.w);
    }
    // reduce across the 8 slots (lanes with equal (lane&3) hold same channel group)
#pragma unroll
    for (int off = 4; off < 32; off <<= 1) {
        acc.x += __shfl_xor_sync(0xffffffffu, acc.x, off);
        acc.y += __shfl_xor_sync(0xffffffffu, acc.y, off);
        acc.z += __shfl_xor_sync(0xffffffffu, acc.z, off);
        acc.w += __shfl_xor_sync(0xffffffffu, acc.w, off);
        dn    += __shfl_xor_sync(0xffffffffu, dn,    off);
    }
    if (slot == 0) {
        float inv = 1.f / (dn + 1e-16f);
        float4 b = *(const float4*)(bias2 + cg);
        float4 o;
        o.x = elu1(fmaf(acc.x, inv, b.x));
        o.y = elu1(fmaf(acc.y, inv, b.y));
        o.z = elu1(fmaf(acc.z, inv, b.z));
        o.w = elu1(fmaf(acc.w, inv, b.w));
        int g = batch[n];
        float* p = g_pool + g * HID + cg;
        atomicAdd(p + 0, o.x);
        atomicAdd(p + 1, o.y);
        atomicAdd(p + 2, o.z);
        atomicAdd(p + 3, o.w);
        if (lane == 0) atomicAdd(&g_cnt[g], 1.f);
    }
}

// ---------------- mean + MLP -------------------------------------------------
__global__ void mlp_kernel(const float* __restrict__ w1, const float* __restrict__ b1,
                           const float* __restrict__ w2, const float* __restrict__ b2,
                           const float* __restrict__ w3, const float* __restrict__ b3,
                           float* __restrict__ out) {
    int g = blockIdx.x * blockDim.x + threadIdx.x;
    if (g >= BG) return;
    float cnt = fmaxf(g_cnt[g], 1.f);
    float h[HID];
#pragma unroll
    for (int k = 0; k < HID; k++) h[k] = g_pool[g * HID + k] / cnt;
    float t1[2 * HID];
#pragma unroll
    for (int j = 0; j < 2 * HID; j++) {
        float s = b1[j];
#pragma unroll
        for (int k = 0; k < HID; k++) s = fmaf(h[k], w1[k * 2 * HID + j], s);
        t1[j] = elu1(s);
    }
    float t2[HID];
#pragma unroll
    for (int k = 0; k < HID; k++) {
        float s = b2[k];
#pragma unroll
        for (int j = 0; j < 2 * HID; j++) s = fmaf(t1[j], w2[j * HID + k], s);
        t2[k] = elu1(s);
    }
#pragma unroll
    for (int o = 0; o < OUTC; o++) {
        float s = b3[o];
#pragma unroll
        for (int k = 0; k < HID; k++) s = fmaf(t2[k], w3[k * OUTC + o], s);
        out[g * OUTC + o] = s;
    }
}

// ---------------- launch -----------------------------------------------------
extern "C" void kernel_launch(void* const* d_in, const int* in_sizes, int n_in,
                              void* d_out, int out_size) {
    const float* x    = (const float*)d_in[0];
    const int*   ei   = (const int*)  d_in[1];
    const int*   batch= (const int*)  d_in[2];
    const float* wl1  = (const float*)d_in[3];
    const float* bl1  = (const float*)d_in[4];
    const float* wr1  = (const float*)d_in[5];
    const float* br1  = (const float*)d_in[6];
    const float* att1 = (const float*)d_in[7];
    const float* bias1= (const float*)d_in[8];
    const float* wl2  = (const float*)d_in[9];
    const float* bl2  = (const float*)d_in[10];
    const float* wr2  = (const float*)d_in[11];
    const float* br2  = (const float*)d_in[12];
    const float* att2 = (const float*)d_in[13];
    const float* bias2= (const float*)d_in[14];
    const float* w_m1 = (const float*)d_in[15];
    const float* b_m1 = (const float*)d_in[16];
    const float* w_m2 = (const float*)d_in[17];
    const float* b_m2 = (const float*)d_in[18];
    const float* w_m3 = (const float*)d_in[19];
    const float* b_m3 = (const float*)d_in[20];
    float* out = (float*)d_out;

    const int TB = 256;

    zero_small<<<80, TB>>>();
    csr_hist<<<(EE + TB - 1) / TB, TB>>>(ei);
    csr_scan<<<1, 1024>>>();
    csr_fill<<<(EE + TB - 1) / TB, TB>>>(ei);
    transform1_tiled<<<NN / 16, C1>>>(x, wl1, bl1, wr1, br1);
    gat1_gather<<<(NN * 32 + TB - 1) / TB, TB>>>(att1, bias1);
    transform2<<<(NN * HID + TB - 1) / TB, TB>>>(wl2, bl2, wr2, br2);
    gat2_gather<<<(NN * 32 + TB - 1) / TB, TB>>>(att2, bias2, batch);
    mlp_kernel<<<1, BG>>>(w_m1, b_m1, w_m2, b_m2, w_m3, b_m3, out);
}